// round 7
// baseline (speedup 1.0000x reference)
#include <cuda_runtime.h>
#include <cstdint>

#define S_  16
#define T_  400
#define F_  16
#define SF_ 250
#define G_  4
#define H1  32
#define H2  16

#define THREADS  512
#define CHUNKS   9
#define ROWS_S   (T_ * (SF_ + 1))                    // 100400
#define ROWS_CTA ((ROWS_S + CHUNKS - 1) / CHUNKS)    // 11156

#define NPR       (G_ * T_)        // 1600 P rows, r = g*400 + t
#define P_FLOATS  (NPR * H1)       // 51200
// smem (floats): P | W1eff[512] | W2[512] | B1[32] | B2[16] | W3[16]
#define OFF_W1    P_FLOATS
#define OFF_W2    (OFF_W1 + 512)
#define OFF_B1    (OFF_W2 + 512)
#define OFF_B2    (OFF_B1 + 32)
#define OFF_W3    (OFF_B2 + 16)
#define SMEM_FLOATS (OFF_W3 + 16)
#define SMEM_BYTES  (SMEM_FLOATS * 4)   // 209,216 B

typedef unsigned long long ull;

__device__ __forceinline__ ull pk2(float a, float b) {
    ull r; asm("mov.b64 %0, {%1,%2};" : "=l"(r) : "f"(a), "f"(b)); return r;
}
__device__ __forceinline__ void upk(ull p, float& a, float& b) {
    asm("mov.b64 {%0,%1}, %2;" : "=f"(a), "=f"(b) : "l"(p));
}
__device__ __forceinline__ ull fma2(ull a, ull b, ull c) {
    ull d; asm("fma.rn.f32x2 %0, %1, %2, %3;" : "=l"(d) : "l"(a), "l"(b), "l"(c)); return d;
}
__device__ __forceinline__ ull add2(ull a, ull b) {
    ull d; asm("add.rn.f32x2 %0, %1, %2;" : "=l"(d) : "l"(a), "l"(b)); return d;
}
__device__ __forceinline__ float lrelu(float x) { return fmaxf(x, 0.01f * x); }

struct RowIdx { int t0, t1, t2, t3; };

__device__ __forceinline__ RowIdx load_idx(const int* __restrict__ perm, int s, int idx) {
    RowIdx r;
    int sfp = idx / T_;
    int t   = idx - sfp * T_;
    if (sfp == 0) { r.t0 = r.t1 = r.t2 = r.t3 = t; }
    else {
        int base = ((sfp - 1) * (G_ * S_) + s) * T_ + t;
        r.t0 = perm[base];
        r.t1 = perm[base + S_ * T_];
        r.t2 = perm[base + 2 * S_ * T_];
        r.t3 = perm[base + 3 * S_ * T_];
    }
    return r;
}

// swizzled P base (byte offset) for P row r: quads live at base ^ (q<<4)
__device__ __forceinline__ uint32_t pbase(int r) {
    return ((uint32_t)r << 7) | (((uint32_t)r & 7u) << 4);
}

__global__ __launch_bounds__(THREADS, 1)
void fused_kernel(const float* __restrict__ obs,
                  const float* __restrict__ mu,
                  const float* __restrict__ Sig,
                  const int*   __restrict__ perm,
                  const float* __restrict__ W1,
                  const float* __restrict__ b1,
                  const float* __restrict__ W2,
                  const float* __restrict__ b2,
                  const float* __restrict__ W3,
                  const float* __restrict__ b3,
                  float* __restrict__ out) {
    extern __shared__ __align__(16) char sm[];
    float* smf = (float*)sm;
    float* sW1 = smf + OFF_W1;
    float* sW2 = smf + OFF_W2;
    float* sB1 = smf + OFF_B1;
    float* sB2 = smf + OFF_B2;
    float* sW3 = smf + OFF_W3;

    const int s   = blockIdx.y;
    const int k   = blockIdx.x;
    const int tid = threadIdx.x;

    // ---- W1eff = Sigma^T W1 (normalize folded into layer 1) ----
    for (int m = tid; m < F_ * H1; m += THREADS) {
        int j = m >> 5, c = m & 31;
        float acc = 0.f;
        #pragma unroll
        for (int i = 0; i < F_; i++) acc += Sig[i * F_ + j] * W1[i * H1 + c];
        sW1[j * H1 + c] = acc;
    }
    // ---- b1eff = b1 - mu^T W1eff (gmem only, no dependency on sW1) ----
    if (tid < H1) {
        int c = tid;
        float bacc = 0.f;
        #pragma unroll
        for (int j = 0; j < F_; j++) {
            float wj = 0.f;
            #pragma unroll
            for (int i = 0; i < F_; i++) wj += Sig[i * F_ + j] * W1[i * H1 + c];
            bacc += mu[j] * wj;
        }
        sB1[c] = b1[c] - bacc;
    }
    for (int m = tid; m < H1 * H2; m += THREADS) sW2[m] = W2[m];
    if (tid < H2) sB2[tid] = b2[tid];
    if (tid < H2) sW3[tid] = W3[tid];
    __syncthreads();   // sW1 ready for P build

    // ---- build P table: P[r=g*400+t][c] = dot(obs[s,t,4g:4g+4], W1eff[4g:,c]) ----
    // stored swizzled: pair cp of row r at byte pbase(r) ^ ((cp>>1)<<4) | ((cp&1)<<3)
    const float* obsS = obs + s * (T_ * F_);
    for (int ep = tid; ep < NPR * 16; ep += THREADS) {
        int cp = ep & 15;            // c-pair index (c = 2cp, 2cp+1)
        int r  = ep >> 4;            // 0..1599
        int g  = r / T_;
        int t  = r - g * T_;
        float4 x = *(const float4*)(obsS + t * F_ + g * 4);
        const float* wb = sW1 + (g * 4) * H1 + 2 * cp;
        ull acc = fma2(pk2(x.x, x.x), *(const ull*)(wb), 0ULL);
        acc = fma2(pk2(x.y, x.y), *(const ull*)(wb + H1), acc);
        acc = fma2(pk2(x.z, x.z), *(const ull*)(wb + 2 * H1), acc);
        acc = fma2(pk2(x.w, x.w), *(const ull*)(wb + 3 * H1), acc);
        uint32_t off = pbase(r) ^ (((uint32_t)(cp >> 1)) << 4);
        *(ull*)(sm + off + ((cp & 1) << 3)) = acc;
    }
    __syncthreads();

    const float b3v = b3[0];
    const int rowsBeg = k * ROWS_CTA;
    const int rowsEnd = (rowsBeg + ROWS_CTA < ROWS_S) ? rowsBeg + ROWS_CTA : ROWS_S;
    float* outS = out + s * ROWS_S;

    const int stride = 2 * THREADS;
    int idxA = rowsBeg + tid;
    if (idxA >= rowsEnd) return;

    int idxB = idxA + THREADS;
    bool hasB = (idxB < rowsEnd);
    RowIdx ra = load_idx(perm, s, idxA);
    RowIdx rb = load_idx(perm, s, hasB ? idxB : idxA);

    while (true) {
        const int curA = idxA, curB = hasB ? idxB : idxA;
        const bool curHasB = hasB;

        // swizzled P row bases for both rows (byte offsets)
        uint32_t aB0 = pbase(0 * T_ + ra.t0), aB1 = pbase(1 * T_ + ra.t1);
        uint32_t aB2 = pbase(2 * T_ + ra.t2), aB3 = pbase(3 * T_ + ra.t3);
        uint32_t bB0 = pbase(0 * T_ + rb.t0), bB1 = pbase(1 * T_ + rb.t1);
        uint32_t bB2 = pbase(2 * T_ + rb.t2), bB3 = pbase(3 * T_ + rb.t3);

        // ---- prefetch next iteration's perm indices ----
        idxA += stride;
        const bool more = (idxA < rowsEnd);
        if (more) {
            idxB = idxA + THREADS;
            hasB = (idxB < rowsEnd);
            ra = load_idx(perm, s, idxA);
            rb = load_idx(perm, s, hasB ? idxB : idxA);
        }

        // ---- layer-2 accumulators (init with b2) ----
        ull cA2[8], cB2[8];
        {
            const ull* pb = (const ull*)sB2;
            #pragma unroll
            for (int p = 0; p < 8; p++) { cA2[p] = pb[p]; cB2[p] = pb[p]; }
        }

        // ---- h1 in two 16-wide halves: gather-accumulate P rows, then lrelu+layer2 ----
        #pragma unroll
        for (int half = 0; half < 2; half++) {
            ull hA[8], hB[8];
            {
                const ull* pb = (const ull*)(sB1 + half * 16);
                #pragma unroll
                for (int p = 0; p < 8; p++) { hA[p] = pb[p]; hB[p] = pb[p]; }
            }
            // gather quads q = half*4 .. half*4+3 from each of the 4 group rows
            #pragma unroll
            for (int q = half * 4; q < half * 4 + 4; q++) {
                const uint32_t qx = (uint32_t)q << 4;
                int hp = (q - half * 4) * 2;
                ulonglong2 v;
                v = *(const ulonglong2*)(sm + (aB0 ^ qx));
                hA[hp] = add2(hA[hp], v.x); hA[hp + 1] = add2(hA[hp + 1], v.y);
                v = *(const ulonglong2*)(sm + (aB1 ^ qx));
                hA[hp] = add2(hA[hp], v.x); hA[hp + 1] = add2(hA[hp + 1], v.y);
                v = *(const ulonglong2*)(sm + (aB2 ^ qx));
                hA[hp] = add2(hA[hp], v.x); hA[hp + 1] = add2(hA[hp + 1], v.y);
                v = *(const ulonglong2*)(sm + (aB3 ^ qx));
                hA[hp] = add2(hA[hp], v.x); hA[hp + 1] = add2(hA[hp + 1], v.y);
                v = *(const ulonglong2*)(sm + (bB0 ^ qx));
                hB[hp] = add2(hB[hp], v.x); hB[hp + 1] = add2(hB[hp + 1], v.y);
                v = *(const ulonglong2*)(sm + (bB1 ^ qx));
                hB[hp] = add2(hB[hp], v.x); hB[hp + 1] = add2(hB[hp + 1], v.y);
                v = *(const ulonglong2*)(sm + (bB2 ^ qx));
                hB[hp] = add2(hB[hp], v.x); hB[hp + 1] = add2(hB[hp + 1], v.y);
                v = *(const ulonglong2*)(sm + (bB3 ^ qx));
                hB[hp] = add2(hB[hp], v.x); hB[hp + 1] = add2(hB[hp + 1], v.y);
            }
            // lrelu + accumulate into layer-2 partials
            #pragma unroll
            for (int p = 0; p < 8; p++) {
                float u, v;
                upk(hA[p], u, v);
                float au = lrelu(u), av = lrelu(v);
                upk(hB[p], u, v);
                float bu = lrelu(u), bv = lrelu(v);
                ull au2 = pk2(au, au), av2 = pk2(av, av);
                ull bu2 = pk2(bu, bu), bv2 = pk2(bv, bv);
                int i0 = half * 16 + 2 * p;
                const ulonglong2* w0 = (const ulonglong2*)(sW2 + i0 * H2);
                const ulonglong2* w1 = (const ulonglong2*)(sW2 + (i0 + 1) * H2);
                #pragma unroll
                for (int q = 0; q < 4; q++) {
                    ulonglong2 wu = w0[q];
                    ulonglong2 wv = w1[q];
                    cA2[2 * q]     = fma2(au2, wu.x, cA2[2 * q]);
                    cA2[2 * q + 1] = fma2(au2, wu.y, cA2[2 * q + 1]);
                    cB2[2 * q]     = fma2(bu2, wu.x, cB2[2 * q]);
                    cB2[2 * q + 1] = fma2(bu2, wu.y, cB2[2 * q + 1]);
                    cA2[2 * q]     = fma2(av2, wv.x, cA2[2 * q]);
                    cA2[2 * q + 1] = fma2(av2, wv.y, cA2[2 * q + 1]);
                    cB2[2 * q]     = fma2(bv2, wv.x, cB2[2 * q]);
                    cB2[2 * q + 1] = fma2(bv2, wv.y, cB2[2 * q + 1]);
                }
            }
        }

        // ---- layer 3 + sigmoid ----
        float zA = b3v, zB = b3v;
        #pragma unroll
        for (int p = 0; p < 8; p++) {
            float u, v;
            upk(cA2[p], u, v); zA += lrelu(u) * sW3[2 * p] + lrelu(v) * sW3[2 * p + 1];
            upk(cB2[p], u, v); zB += lrelu(u) * sW3[2 * p] + lrelu(v) * sW3[2 * p + 1];
        }
        outS[curA] = 1.f / (1.f + __expf(-zA));
        if (curHasB) outS[curB] = 1.f / (1.f + __expf(-zB));

        if (!more) break;
    }
}

extern "C" void kernel_launch(void* const* d_in, const int* in_sizes, int n_in,
                              void* d_out, int out_size) {
    const float* obs  = (const float*)d_in[0];
    const float* mu   = (const float*)d_in[1];
    const float* Sig  = (const float*)d_in[2];
    const int*   perm = (const int*)d_in[3];
    const float* W1   = (const float*)d_in[4];
    const float* b1   = (const float*)d_in[5];
    const float* W2   = (const float*)d_in[6];
    const float* b2   = (const float*)d_in[7];
    const float* W3   = (const float*)d_in[8];
    const float* b3   = (const float*)d_in[9];
    float* out = (float*)d_out;

    cudaFuncSetAttribute(fused_kernel, cudaFuncAttributeMaxDynamicSharedMemorySize, SMEM_BYTES);

    dim3 grid(CHUNKS, S_);
    fused_kernel<<<grid, THREADS, SMEM_BYTES>>>(obs, mu, Sig, perm, W1, b1, W2, b2, W3, b3, out);
}

// round 8
// speedup vs baseline: 1.0003x; 1.0003x over previous
#include <cuda_runtime.h>
#include <cstdint>

#define S_  16
#define T_  400
#define F_  16
#define SF_ 250
#define G_  4
#define H1  32
#define H2  16

#define THREADS  512
#define CHUNKS   9
#define ROWS_S   (T_ * (SF_ + 1))                    // 100400
#define ROWS_CTA ((ROWS_S + CHUNKS - 1) / CHUNKS)    // 11156

#define NPR       (G_ * T_)        // 1600 P rows, r = g*400 + t
#define P_FLOATS  (NPR * H1)       // 51200
// smem (floats): P | W1eff[512] | W2[512] | B1[32] | B2[16] | W3[16]
#define OFF_W1    P_FLOATS
#define OFF_W2    (OFF_W1 + 512)
#define OFF_B1    (OFF_W2 + 512)
#define OFF_B2    (OFF_B1 + 32)
#define OFF_W3    (OFF_B2 + 16)
#define SMEM_FLOATS (OFF_W3 + 16)
#define SMEM_BYTES  (SMEM_FLOATS * 4)   // 209,216 B

typedef unsigned long long ull;

__device__ __forceinline__ ull pk2(float a, float b) {
    ull r; asm("mov.b64 %0, {%1,%2};" : "=l"(r) : "f"(a), "f"(b)); return r;
}
__device__ __forceinline__ void upk(ull p, float& a, float& b) {
    asm("mov.b64 {%0,%1}, %2;" : "=f"(a), "=f"(b) : "l"(p));
}
__device__ __forceinline__ ull fma2(ull a, ull b, ull c) {
    ull d; asm("fma.rn.f32x2 %0, %1, %2, %3;" : "=l"(d) : "l"(a), "l"(b), "l"(c)); return d;
}
__device__ __forceinline__ ull add2(ull a, ull b) {
    ull d; asm("add.rn.f32x2 %0, %1, %2;" : "=l"(d) : "l"(a), "l"(b)); return d;
}
__device__ __forceinline__ float lrelu(float x) { return fmaxf(x, 0.01f * x); }

struct RowIdx { int t0, t1, t2, t3; };

__device__ __forceinline__ RowIdx load_idx(const int* __restrict__ perm, int s, int idx) {
    RowIdx r;
    int sfp = idx / T_;
    int t   = idx - sfp * T_;
    if (sfp == 0) { r.t0 = r.t1 = r.t2 = r.t3 = t; }
    else {
        int base = ((sfp - 1) * (G_ * S_) + s) * T_ + t;
        r.t0 = perm[base];
        r.t1 = perm[base + S_ * T_];
        r.t2 = perm[base + 2 * S_ * T_];
        r.t3 = perm[base + 3 * S_ * T_];
    }
    return r;
}

// swizzled P base (byte offset) for P row r: quads live at base ^ (q<<4)
__device__ __forceinline__ uint32_t pbase(int r) {
    return ((uint32_t)r << 7) | (((uint32_t)r & 7u) << 4);
}

__global__ __launch_bounds__(THREADS, 1)
void fused_kernel(const float* __restrict__ obs,
                  const float* __restrict__ mu,
                  const float* __restrict__ Sig,
                  const int*   __restrict__ perm,
                  const float* __restrict__ W1,
                  const float* __restrict__ b1,
                  const float* __restrict__ W2,
                  const float* __restrict__ b2,
                  const float* __restrict__ W3,
                  const float* __restrict__ b3,
                  float* __restrict__ out) {
    extern __shared__ __align__(16) char sm[];
    float* smf = (float*)sm;
    float* sW1 = smf + OFF_W1;
    float* sW2 = smf + OFF_W2;
    float* sB1 = smf + OFF_B1;
    float* sB2 = smf + OFF_B2;
    float* sW3 = smf + OFF_W3;

    const int s   = blockIdx.y;
    const int k   = blockIdx.x;
    const int tid = threadIdx.x;

    // ---- W1eff = Sigma^T W1 (normalize folded into layer 1) ----
    for (int m = tid; m < F_ * H1; m += THREADS) {
        int j = m >> 5, c = m & 31;
        float acc = 0.f;
        #pragma unroll
        for (int i = 0; i < F_; i++) acc += Sig[i * F_ + j] * W1[i * H1 + c];
        sW1[j * H1 + c] = acc;
    }
    // ---- b1eff = b1 - mu^T W1eff (gmem only, no dependency on sW1) ----
    if (tid < H1) {
        int c = tid;
        float bacc = 0.f;
        #pragma unroll
        for (int j = 0; j < F_; j++) {
            float wj = 0.f;
            #pragma unroll
            for (int i = 0; i < F_; i++) wj += Sig[i * F_ + j] * W1[i * H1 + c];
            bacc += mu[j] * wj;
        }
        sB1[c] = b1[c] - bacc;
    }
    for (int m = tid; m < H1 * H2; m += THREADS) sW2[m] = W2[m];
    if (tid < H2) sB2[tid] = b2[tid];
    if (tid < H2) sW3[tid] = W3[tid];
    __syncthreads();   // sW1 ready for P build

    // ---- build P table: P[r=g*400+t][c] = dot(obs[s,t,4g:4g+4], W1eff[4g:,c]) ----
    // stored swizzled: pair cp of row r at byte pbase(r) ^ ((cp>>1)<<4) | ((cp&1)<<3)
    const float* obsS = obs + s * (T_ * F_);
    for (int ep = tid; ep < NPR * 16; ep += THREADS) {
        int cp = ep & 15;            // c-pair index (c = 2cp, 2cp+1)
        int r  = ep >> 4;            // 0..1599
        int g  = r / T_;
        int t  = r - g * T_;
        float4 x = *(const float4*)(obsS + t * F_ + g * 4);
        const float* wb = sW1 + (g * 4) * H1 + 2 * cp;
        ull acc = fma2(pk2(x.x, x.x), *(const ull*)(wb), 0ULL);
        acc = fma2(pk2(x.y, x.y), *(const ull*)(wb + H1), acc);
        acc = fma2(pk2(x.z, x.z), *(const ull*)(wb + 2 * H1), acc);
        acc = fma2(pk2(x.w, x.w), *(const ull*)(wb + 3 * H1), acc);
        uint32_t off = pbase(r) ^ (((uint32_t)(cp >> 1)) << 4);
        *(ull*)(sm + off + ((cp & 1) << 3)) = acc;
    }
    __syncthreads();

    const float b3v = b3[0];
    const int rowsBeg = k * ROWS_CTA;
    const int rowsEnd = (rowsBeg + ROWS_CTA < ROWS_S) ? rowsBeg + ROWS_CTA : ROWS_S;
    float* outS = out + s * ROWS_S;

    const int stride = 2 * THREADS;
    int idxA = rowsBeg + tid;
    if (idxA >= rowsEnd) return;

    int idxB = idxA + THREADS;
    bool hasB = (idxB < rowsEnd);
    RowIdx ra = load_idx(perm, s, idxA);
    RowIdx rb = load_idx(perm, s, hasB ? idxB : idxA);

    while (true) {
        const int curA = idxA, curB = hasB ? idxB : idxA;
        const bool curHasB = hasB;

        // swizzled P row bases for both rows (byte offsets)
        uint32_t aB0 = pbase(0 * T_ + ra.t0), aB1 = pbase(1 * T_ + ra.t1);
        uint32_t aB2 = pbase(2 * T_ + ra.t2), aB3 = pbase(3 * T_ + ra.t3);
        uint32_t bB0 = pbase(0 * T_ + rb.t0), bB1 = pbase(1 * T_ + rb.t1);
        uint32_t bB2 = pbase(2 * T_ + rb.t2), bB3 = pbase(3 * T_ + rb.t3);

        // ---- prefetch next iteration's perm indices ----
        idxA += stride;
        const bool more = (idxA < rowsEnd);
        if (more) {
            idxB = idxA + THREADS;
            hasB = (idxB < rowsEnd);
            ra = load_idx(perm, s, idxA);
            rb = load_idx(perm, s, hasB ? idxB : idxA);
        }

        // ---- layer-2 accumulators (init with b2) ----
        ull cA2[8], cB2[8];
        {
            const ull* pb = (const ull*)sB2;
            #pragma unroll
            for (int p = 0; p < 8; p++) { cA2[p] = pb[p]; cB2[p] = pb[p]; }
        }

        // ---- h1 in two 16-wide halves: gather-accumulate P rows, then lrelu+layer2 ----
        #pragma unroll
        for (int half = 0; half < 2; half++) {
            ull hA[8], hB[8];
            {
                const ull* pb = (const ull*)(sB1 + half * 16);
                #pragma unroll
                for (int p = 0; p < 8; p++) { hA[p] = pb[p]; hB[p] = pb[p]; }
            }
            // gather quads q = half*4 .. half*4+3 from each of the 4 group rows
            #pragma unroll
            for (int q = half * 4; q < half * 4 + 4; q++) {
                const uint32_t qx = (uint32_t)q << 4;
                int hp = (q - half * 4) * 2;
                ulonglong2 v;
                v = *(const ulonglong2*)(sm + (aB0 ^ qx));
                hA[hp] = add2(hA[hp], v.x); hA[hp + 1] = add2(hA[hp + 1], v.y);
                v = *(const ulonglong2*)(sm + (aB1 ^ qx));
                hA[hp] = add2(hA[hp], v.x); hA[hp + 1] = add2(hA[hp + 1], v.y);
                v = *(const ulonglong2*)(sm + (aB2 ^ qx));
                hA[hp] = add2(hA[hp], v.x); hA[hp + 1] = add2(hA[hp + 1], v.y);
                v = *(const ulonglong2*)(sm + (aB3 ^ qx));
                hA[hp] = add2(hA[hp], v.x); hA[hp + 1] = add2(hA[hp + 1], v.y);
                v = *(const ulonglong2*)(sm + (bB0 ^ qx));
                hB[hp] = add2(hB[hp], v.x); hB[hp + 1] = add2(hB[hp + 1], v.y);
                v = *(const ulonglong2*)(sm + (bB1 ^ qx));
                hB[hp] = add2(hB[hp], v.x); hB[hp + 1] = add2(hB[hp + 1], v.y);
                v = *(const ulonglong2*)(sm + (bB2 ^ qx));
                hB[hp] = add2(hB[hp], v.x); hB[hp + 1] = add2(hB[hp + 1], v.y);
                v = *(const ulonglong2*)(sm + (bB3 ^ qx));
                hB[hp] = add2(hB[hp], v.x); hB[hp + 1] = add2(hB[hp + 1], v.y);
            }
            // lrelu + accumulate into layer-2 partials
            #pragma unroll
            for (int p = 0; p < 8; p++) {
                float u, v;
                upk(hA[p], u, v);
                float au = lrelu(u), av = lrelu(v);
                upk(hB[p], u, v);
                float bu = lrelu(u), bv = lrelu(v);
                ull au2 = pk2(au, au), av2 = pk2(av, av);
                ull bu2 = pk2(bu, bu), bv2 = pk2(bv, bv);
                int i0 = half * 16 + 2 * p;
                const ulonglong2* w0 = (const ulonglong2*)(sW2 + i0 * H2);
                const ulonglong2* w1 = (const ulonglong2*)(sW2 + (i0 + 1) * H2);
                #pragma unroll
                for (int q = 0; q < 4; q++) {
                    ulonglong2 wu = w0[q];
                    ulonglong2 wv = w1[q];
                    cA2[2 * q]     = fma2(au2, wu.x, cA2[2 * q]);
                    cA2[2 * q + 1] = fma2(au2, wu.y, cA2[2 * q + 1]);
                    cB2[2 * q]     = fma2(bu2, wu.x, cB2[2 * q]);
                    cB2[2 * q + 1] = fma2(bu2, wu.y, cB2[2 * q + 1]);
                    cA2[2 * q]     = fma2(av2, wv.x, cA2[2 * q]);
                    cA2[2 * q + 1] = fma2(av2, wv.y, cA2[2 * q + 1]);
                    cB2[2 * q]     = fma2(bv2, wv.x, cB2[2 * q]);
                    cB2[2 * q + 1] = fma2(bv2, wv.y, cB2[2 * q + 1]);
                }
            }
        }

        // ---- layer 3 + sigmoid ----
        float zA = b3v, zB = b3v;
        #pragma unroll
        for (int p = 0; p < 8; p++) {
            float u, v;
            upk(cA2[p], u, v); zA += lrelu(u) * sW3[2 * p] + lrelu(v) * sW3[2 * p + 1];
            upk(cB2[p], u, v); zB += lrelu(u) * sW3[2 * p] + lrelu(v) * sW3[2 * p + 1];
        }
        outS[curA] = 1.f / (1.f + __expf(-zA));
        if (curHasB) outS[curB] = 1.f / (1.f + __expf(-zB));

        if (!more) break;
    }
}

extern "C" void kernel_launch(void* const* d_in, const int* in_sizes, int n_in,
                              void* d_out, int out_size) {
    const float* obs  = (const float*)d_in[0];
    const float* mu   = (const float*)d_in[1];
    const float* Sig  = (const float*)d_in[2];
    const int*   perm = (const int*)d_in[3];
    const float* W1   = (const float*)d_in[4];
    const float* b1   = (const float*)d_in[5];
    const float* W2   = (const float*)d_in[6];
    const float* b2   = (const float*)d_in[7];
    const float* W3   = (const float*)d_in[8];
    const float* b3   = (const float*)d_in[9];
    float* out = (float*)d_out;

    cudaFuncSetAttribute(fused_kernel, cudaFuncAttributeMaxDynamicSharedMemorySize, SMEM_BYTES);

    dim3 grid(CHUNKS, S_);
    fused_kernel<<<grid, THREADS, SMEM_BYTES>>>(obs, mu, Sig, perm, W1, b1, W2, b2, W3, b3, out);
}

// round 9
// speedup vs baseline: 1.3398x; 1.3394x over previous
#include <cuda_runtime.h>

#define S_  16
#define T_  400
#define F_  16
#define SF_ 250
#define G_  4
#define H1  32
#define H2  16

#define OBS_STRIDE 20
#define THREADS    256
#define R_         4
#define CHUNKS     9
#define ROWS_S     (T_ * (SF_ + 1))                    // 100400
#define ROWS_CTA   ((ROWS_S + CHUNKS - 1) / CHUNKS)    // 11156

typedef unsigned long long ull;

__device__ __forceinline__ ull pk2(float a, float b) {
    ull r; asm("mov.b64 %0, {%1,%2};" : "=l"(r) : "f"(a), "f"(b)); return r;
}
__device__ __forceinline__ void upk(ull p, float& a, float& b) {
    asm("mov.b64 {%0,%1}, %2;" : "=f"(a), "=f"(b) : "l"(p));
}
__device__ __forceinline__ ull fma2(ull a, ull b, ull c) {
    ull d; asm("fma.rn.f32x2 %0, %1, %2, %3;" : "=l"(d) : "l"(a), "l"(b), "l"(c)); return d;
}
__device__ __forceinline__ float lrelu(float x) { return fmaxf(x, 0.01f * x); }

struct RowIdx { int t[G_]; };

__device__ __forceinline__ RowIdx load_idx(const int* __restrict__ perm, int s, int idx) {
    RowIdx r;
    int sfp = idx / T_;
    int t   = idx - sfp * T_;
    if (sfp == 0) { r.t[0] = r.t[1] = r.t[2] = r.t[3] = t; }
    else {
        int base = ((sfp - 1) * (G_ * S_) + s) * T_ + t;
        r.t[0] = perm[base];
        r.t[1] = perm[base + S_ * T_];
        r.t[2] = perm[base + 2 * S_ * T_];
        r.t[3] = perm[base + 3 * S_ * T_];
    }
    return r;
}

__global__ __launch_bounds__(THREADS, 1)
void fused_kernel(const float* __restrict__ obs,
                  const float* __restrict__ mu,
                  const float* __restrict__ Sig,
                  const int*   __restrict__ perm,
                  const float* __restrict__ W1,
                  const float* __restrict__ b1,
                  const float* __restrict__ W2,
                  const float* __restrict__ b2,
                  const float* __restrict__ W3,
                  const float* __restrict__ b3,
                  float* __restrict__ out) {
    __shared__ __align__(16) float sObs[T_ * OBS_STRIDE];  // 32000 B
    __shared__ __align__(16) float sW1[F_ * H1];           // W1eff [j][c]
    __shared__ __align__(16) float sW2[H1 * H2];           // [i][j]
    __shared__ __align__(16) float sB1[H1];
    __shared__ __align__(16) float sB2[H2];
    __shared__ __align__(16) float sW3[H2];

    const int s   = blockIdx.y;
    const int k   = blockIdx.x;
    const int tid = threadIdx.x;

    // ---- stage obs slice (padded rows) ----
    const float4* osrc = (const float4*)(obs + s * (T_ * F_));
    for (int m = tid; m < T_ * F_ / 4; m += THREADS) {
        int t = m >> 2, q = m & 3;
        *(float4*)(sObs + t * OBS_STRIDE + q * 4) = osrc[m];
    }
    // ---- W1eff = Sigma^T W1 (normalize folded into layer 1) ----
    for (int m = tid; m < F_ * H1; m += THREADS) {
        int j = m >> 5, c = m & 31;
        float acc = 0.f;
        #pragma unroll
        for (int i = 0; i < F_; i++) acc += Sig[i * F_ + j] * W1[i * H1 + c];
        sW1[j * H1 + c] = acc;
    }
    // ---- b1eff = b1 - mu^T W1eff ----
    if (tid < H1) {
        int c = tid;
        float bacc = 0.f;
        #pragma unroll
        for (int j = 0; j < F_; j++) {
            float wj = 0.f;
            #pragma unroll
            for (int i = 0; i < F_; i++) wj += Sig[i * F_ + j] * W1[i * H1 + c];
            bacc += mu[j] * wj;
        }
        sB1[c] = b1[c] - bacc;
    }
    for (int m = tid; m < H1 * H2; m += THREADS) sW2[m] = W2[m];
    if (tid < H2) sB2[tid] = b2[tid];
    if (tid < H2) sW3[tid] = W3[tid];
    __syncthreads();

    const float b3v = b3[0];
    const int rowsBeg = k * ROWS_CTA;
    const int rowsEnd = (rowsBeg + ROWS_CTA < ROWS_S) ? rowsBeg + ROWS_CTA : ROWS_S;
    float* outS = out + s * ROWS_S;

    int idx0 = rowsBeg + tid;
    if (idx0 >= rowsEnd) return;

    // prime prefetch (clamp duplicates; stores are guarded later)
    RowIdx ra[R_];
    #pragma unroll
    for (int r = 0; r < R_; r++) {
        int id = idx0 + r * THREADS;
        ra[r] = load_idx(perm, s, id < rowsEnd ? id : rowsEnd - 1);
    }

    while (true) {
        const int curBase = idx0;
        RowIdx ci[R_];
        #pragma unroll
        for (int r = 0; r < R_; r++) ci[r] = ra[r];

        // ---- prefetch next iteration's perm indices ----
        idx0 += R_ * THREADS;
        const bool more = (idx0 < rowsEnd);
        if (more) {
            #pragma unroll
            for (int r = 0; r < R_; r++) {
                int id = idx0 + r * THREADS;
                ra[r] = load_idx(perm, s, id < rowsEnd ? id : rowsEnd - 1);
            }
        }

        // ---- layer-2 accumulators (init with b2) ----
        ull c2[R_][8];
        {
            const ull* pb = (const ull*)sB2;
            #pragma unroll
            for (int r = 0; r < R_; r++)
                #pragma unroll
                for (int p = 0; p < 8; p++) c2[r][p] = pb[p];
        }

        // ---- layer 1 in two 16-wide halves, group-wise gather ----
        #pragma unroll
        for (int half = 0; half < 2; half++) {
            ull h[R_][8];
            {
                const ull* pb = (const ull*)(sB1 + half * 16);
                #pragma unroll
                for (int r = 0; r < R_; r++)
                    #pragma unroll
                    for (int p = 0; p < 8; p++) h[r][p] = pb[p];
            }
            #pragma unroll
            for (int g = 0; g < G_; g++) {
                float4 xg[R_];
                #pragma unroll
                for (int r = 0; r < R_; r++)
                    xg[r] = *(const float4*)(sObs + ci[r].t[g] * OBS_STRIDE + g * 4);
                #pragma unroll
                for (int jj = 0; jj < 4; jj++) {
                    const ulonglong2* w =
                        (const ulonglong2*)(sW1 + (4 * g + jj) * H1 + half * 16);
                    ulonglong2 w0 = w[0], w1 = w[1], w2 = w[2], w3 = w[3];
                    #pragma unroll
                    for (int r = 0; r < R_; r++) {
                        const float* xp = (const float*)&xg[r];
                        ull xj = pk2(xp[jj], xp[jj]);
                        h[r][0] = fma2(xj, w0.x, h[r][0]);
                        h[r][1] = fma2(xj, w0.y, h[r][1]);
                        h[r][2] = fma2(xj, w1.x, h[r][2]);
                        h[r][3] = fma2(xj, w1.y, h[r][3]);
                        h[r][4] = fma2(xj, w2.x, h[r][4]);
                        h[r][5] = fma2(xj, w2.y, h[r][5]);
                        h[r][6] = fma2(xj, w3.x, h[r][6]);
                        h[r][7] = fma2(xj, w3.y, h[r][7]);
                    }
                }
            }
            // ---- lrelu + layer-2 accumulation ----
            #pragma unroll
            for (int p = 0; p < 8; p++) {
                int i0 = half * 16 + 2 * p;
                const ulonglong2* wu = (const ulonglong2*)(sW2 + i0 * H2);
                const ulonglong2* wv = (const ulonglong2*)(sW2 + (i0 + 1) * H2);
                ulonglong2 u0 = wu[0], u1 = wu[1], u2 = wu[2], u3 = wu[3];
                ulonglong2 v0 = wv[0], v1 = wv[1], v2 = wv[2], v3 = wv[3];
                #pragma unroll
                for (int r = 0; r < R_; r++) {
                    float a, b;
                    upk(h[r][p], a, b);
                    float au = lrelu(a), av = lrelu(b);
                    ull au2 = pk2(au, au), av2 = pk2(av, av);
                    c2[r][0] = fma2(au2, u0.x, c2[r][0]);
                    c2[r][1] = fma2(au2, u0.y, c2[r][1]);
                    c2[r][2] = fma2(au2, u1.x, c2[r][2]);
                    c2[r][3] = fma2(au2, u1.y, c2[r][3]);
                    c2[r][4] = fma2(au2, u2.x, c2[r][4]);
                    c2[r][5] = fma2(au2, u2.y, c2[r][5]);
                    c2[r][6] = fma2(au2, u3.x, c2[r][6]);
                    c2[r][7] = fma2(au2, u3.y, c2[r][7]);
                    c2[r][0] = fma2(av2, v0.x, c2[r][0]);
                    c2[r][1] = fma2(av2, v0.y, c2[r][1]);
                    c2[r][2] = fma2(av2, v1.x, c2[r][2]);
                    c2[r][3] = fma2(av2, v1.y, c2[r][3]);
                    c2[r][4] = fma2(av2, v2.x, c2[r][4]);
                    c2[r][5] = fma2(av2, v2.y, c2[r][5]);
                    c2[r][6] = fma2(av2, v3.x, c2[r][6]);
                    c2[r][7] = fma2(av2, v3.y, c2[r][7]);
                }
            }
        }

        // ---- layer 3 + sigmoid + guarded store ----
        #pragma unroll
        for (int r = 0; r < R_; r++) {
            float z = b3v;
            #pragma unroll
            for (int p = 0; p < 8; p++) {
                float u, v;
                upk(c2[r][p], u, v);
                z += lrelu(u) * sW3[2 * p] + lrelu(v) * sW3[2 * p + 1];
            }
            int cid = curBase + r * THREADS;
            if (cid < rowsEnd) outS[cid] = 1.f / (1.f + __expf(-z));
        }

        if (!more) break;
    }
}

extern "C" void kernel_launch(void* const* d_in, const int* in_sizes, int n_in,
                              void* d_out, int out_size) {
    const float* obs  = (const float*)d_in[0];
    const float* mu   = (const float*)d_in[1];
    const float* Sig  = (const float*)d_in[2];
    const int*   perm = (const int*)d_in[3];
    const float* W1   = (const float*)d_in[4];
    const float* b1   = (const float*)d_in[5];
    const float* W2   = (const float*)d_in[6];
    const float* b2   = (const float*)d_in[7];
    const float* W3   = (const float*)d_in[8];
    const float* b3   = (const float*)d_in[9];
    float* out = (float*)d_out;

    dim3 grid(CHUNKS, S_);
    fused_kernel<<<grid, THREADS>>>(obs, mu, Sig, perm, W1, b1, W2, b2, W3, b3, out);
}